// round 7
// baseline (speedup 1.0000x reference)
#include <cuda_runtime.h>
#include <cuda_fp16.h>
#include <cstdint>
#include <math.h>

#define N_    8192
#define D_    256
#define NPID  256
#define CAP   8192
#define NTILE 32

__device__ float    g_normed[N_ * D_];
__device__ __half   g_nh[N_ * D_];
__device__ float    g_hp[N_];
__device__ float    g_validf[N_];
__device__ int      g_colsent[N_];
__device__ int      g_cnt[NPID];
__device__ int      g_list[NPID * CAP];
__device__ unsigned g_aE[N_];   // encoded max over masked negatives (all)
__device__ unsigned g_bE[N_];   // encoded max over masked negatives with v < hp

__device__ __forceinline__ unsigned encf(float f) {
    unsigned u = __float_as_uint(f);
    return (u & 0x80000000u) ? ~u : (u | 0x80000000u);
}
__device__ __forceinline__ float decf(unsigned e) {
    unsigned u = (e & 0x80000000u) ? (e ^ 0x80000000u) : ~e;
    return __uint_as_float(u);
}
__device__ __forceinline__ uint32_t smem_u32(const void* p) {
    uint32_t a;
    asm("{ .reg .u64 t; cvta.to.shared.u64 t, %1; cvt.u32.u64 %0, t; }" : "=r"(a) : "l"(p));
    return a;
}
__device__ __forceinline__ void cpa16(uint32_t d, const void* s) {
    asm volatile("cp.async.cg.shared.global [%0], [%1], 16;" :: "r"(d), "l"(s) : "memory");
}
#define CP_COMMIT() asm volatile("cp.async.commit_group;" ::: "memory")
#define CP_WAIT(n)  asm volatile("cp.async.wait_group %0;" :: "n"(n) : "memory")

__device__ __forceinline__ void ldsm4(uint32_t& r0, uint32_t& r1, uint32_t& r2, uint32_t& r3,
                                      uint32_t addr) {
    asm volatile("ldmatrix.sync.aligned.m8n8.x4.shared.b16 {%0,%1,%2,%3}, [%4];"
                 : "=r"(r0), "=r"(r1), "=r"(r2), "=r"(r3) : "r"(addr));
}
__device__ __forceinline__ void mma16816(float& c0, float& c1, float& c2, float& c3,
                                         uint32_t a0, uint32_t a1, uint32_t a2, uint32_t a3,
                                         uint32_t b0, uint32_t b1) {
    asm volatile("mma.sync.aligned.m16n8k16.row.col.f32.f16.f16.f32 "
                 "{%0,%1,%2,%3},{%4,%5,%6,%7},{%8,%9},{%0,%1,%2,%3};"
                 : "+f"(c0), "+f"(c1), "+f"(c2), "+f"(c3)
                 : "r"(a0), "r"(a1), "r"(a2), "r"(a3), "r"(b0), "r"(b1));
}

// ---------------- normalize + fp16 copy + bucket + init ----------------
__global__ void normalize_k(const float* __restrict__ emb,
                            const int* __restrict__ labels,
                            const int* __restrict__ pids) {
    int j = blockIdx.x, t = threadIdx.x;  // 64 threads, one float4 each
    float4 v = ((const float4*)(emb + (size_t)j * D_))[t];
    float ss = v.x * v.x + v.y * v.y + v.z * v.z + v.w * v.w;
    for (int o = 16; o; o >>= 1) ss += __shfl_xor_sync(0xffffffffu, ss, o);
    __shared__ float sred[2];
    if ((t & 31) == 0) sred[t >> 5] = ss;
    __syncthreads();
    float inv = 1.0f / fmaxf(sqrtf(sred[0] + sred[1]), 1e-12f);
    float4 o4 = make_float4(v.x * inv, v.y * inv, v.z * inv, v.w * inv);
    ((float4*)(g_normed + (size_t)j * D_))[t] = o4;
    __half2 h0 = __floats2half2_rn(o4.x, o4.y);
    __half2 h1 = __floats2half2_rn(o4.z, o4.w);
    ((__half2*)(g_nh + (size_t)j * D_ + t * 4))[0] = h0;
    ((__half2*)(g_nh + (size_t)j * D_ + t * 4))[1] = h1;
    if (t == 0) {
        g_hp[j] = 1e9f;
        g_validf[j] = 0.f;
        unsigned e = encf(-1e9f);
        g_aE[j] = e;
        g_bE[j] = e;
        int lab = labels[j], pid = pids[j];
        g_colsent[j] = (lab == 1) ? pid : -1;
        if (lab == 1) g_list[pid * CAP + atomicAdd(&g_cnt[pid], 1)] = j;
    }
}

__global__ void zero_k() { if (threadIdx.x < NPID) g_cnt[threadIdx.x] = 0; }

// ---------------- hardest positive: block per pid, smem-staged ----------------
__global__ void __launch_bounds__(256, 1)
hp_pid_k() {
    extern __shared__ float srow[];  // up to 64 rows x 256 floats
    int p = blockIdx.x;
    int n = g_cnt[p];
    if (n == 0) return;
    int ns = (n < 64) ? n : 64;
    for (int idx = threadIdx.x; idx < ns * 64; idx += 256) {
        int m = idx >> 6, q = idx & 63;
        ((float4*)srow)[m * 64 + q] =
            ((const float4*)(g_normed + (size_t)g_list[p * CAP + m] * D_))[q];
    }
    __syncthreads();
    int wid = threadIdx.x >> 5, lane = threadIdx.x & 31;
    float vf = (n >= 2) ? 1.f : 0.f;
    for (int a = wid; a < n; a += 8) {
        int i = g_list[p * CAP + a];
        const float* arow = (a < ns) ? (srow + a * D_) : (g_normed + (size_t)i * D_);
        float a8[8];
#pragma unroll
        for (int k = 0; k < 8; k++) a8[k] = arow[k * 32 + lane];
        float hp = 1e9f;
        for (int j = 0; j < n; j++) {
            if (j == a) continue;
            const float* br = (j < ns) ? (srow + j * D_)
                                       : (g_normed + (size_t)g_list[p * CAP + j] * D_);
            float s = 0.f;
#pragma unroll
            for (int k = 0; k < 8; k++) s = fmaf(a8[k], br[k * 32 + lane], s);
            for (int o = 16; o; o >>= 1) s += __shfl_xor_sync(0xffffffffu, s, o);
            hp = fminf(hp, s);
        }
        if (lane == 0) { g_hp[i] = hp; g_validf[i] = vf; }
    }
}

// ---------------- main: mma.sync fp16 GEMM, 1 barrier/tile ----------------
__global__ void __launch_bounds__(256, 1)
main_k(const int* __restrict__ pids) {
    extern __shared__ char sm[];
    uint32_t sb = smem_u32(sm);
    const uint32_t A0 = sb, Bbuf0 = sb + 65536, Bbuf1 = sb + 131072;

    int tid = threadIdx.x, lane = tid & 31, wid = tid >> 5;
    int wr = (wid >> 2) * 64;
    int wc = (wid & 3) * 32;
    int row0 = blockIdx.x * 128;
    int col0 = blockIdx.y * 4096;

    {
        const __half* gs = g_nh + (size_t)row0 * D_;
#pragma unroll
        for (int i = 0; i < 16; i++) {
            int id = tid + i * 256, r = id >> 5, c = id & 31;
            cpa16(A0 + r * 512 + ((c ^ (r & 7)) << 4), gs + r * 256 + c * 8);
        }
        const __half* gb = g_nh + (size_t)col0 * D_;
#pragma unroll
        for (int i = 0; i < 16; i++) {
            int id = tid + i * 256, r = id >> 5, c = id & 31;
            cpa16(Bbuf0 + r * 512 + ((c ^ (r & 7)) << 4), gb + r * 256 + c * 8);
        }
        CP_COMMIT();
    }

    int gid = lane >> 2, tig = lane & 3;
    float hp_s[8], mA[8], mB[8];
    int pid_s[8];
#pragma unroll
    for (int m = 0; m < 4; m++) {
        int rA = row0 + wr + m * 16 + gid;
        hp_s[2 * m] = g_hp[rA];         pid_s[2 * m] = pids[rA];
        hp_s[2 * m + 1] = g_hp[rA + 8]; pid_s[2 * m + 1] = pids[rA + 8];
    }
#pragma unroll
    for (int s = 0; s < 8; s++) { mA[s] = -1e9f; mB[s] = -1e9f; }

    int arow = lane & 15;
    int kha = lane >> 4;
    int brow = ((lane >> 4) & 1) * 8 + (lane & 7);
    int khb = (lane >> 3) & 1;
    int xr = lane & 7;
    uint32_t aAddr[4];
#pragma unroll
    for (int m = 0; m < 4; m++) aAddr[m] = A0 + (wr + m * 16 + arow) * 512;

    for (int t = 0; t < NTILE; t++) {
        CP_WAIT(0);           // B(t) (and A on t=0) complete for this thread
        __syncthreads();      // ...for ALL threads; also: everyone done reading B((t+1)&1)

        if (t + 1 < NTILE) {  // prefetch next tile into the buffer just freed
            uint32_t Bn = (t & 1) ? Bbuf0 : Bbuf1;
            const __half* gs = g_nh + (size_t)(col0 + (t + 1) * 128) * D_;
#pragma unroll
            for (int i = 0; i < 16; i++) {
                int id = tid + i * 256, r = id >> 5, c = id & 31;
                cpa16(Bn + r * 512 + ((c ^ (r & 7)) << 4), gs + r * 256 + c * 8);
            }
            CP_COMMIT();
        }

        // preload epilogue sentinels early (latency hidden behind mma loop)
        int cb = col0 + t * 128 + wc;
        int sv[4][2];
#pragma unroll
        for (int n = 0; n < 4; n++) {
            sv[n][0] = __ldg(&g_colsent[cb + n * 8 + tig * 2]);
            sv[n][1] = __ldg(&g_colsent[cb + n * 8 + tig * 2 + 1]);
        }

        uint32_t Bc = (t & 1) ? Bbuf1 : Bbuf0;
        uint32_t bAddr0 = Bc + (wc + brow) * 512;
        uint32_t bAddr1 = Bc + (wc + 16 + brow) * 512;

        float acc[4][4][4];
#pragma unroll
        for (int m = 0; m < 4; m++)
#pragma unroll
            for (int n = 0; n < 4; n++)
#pragma unroll
                for (int q = 0; q < 4; q++) acc[m][n][q] = 0.f;

#pragma unroll
        for (int ks = 0; ks < 16; ks++) {
            uint32_t aoff = (uint32_t)(((ks * 2 + kha) ^ xr) << 4);
            uint32_t boff = (uint32_t)(((ks * 2 + khb) ^ xr) << 4);
            uint32_t a[4][4], b[2][4];
#pragma unroll
            for (int m = 0; m < 4; m++)
                ldsm4(a[m][0], a[m][1], a[m][2], a[m][3], aAddr[m] + aoff);
            ldsm4(b[0][0], b[0][1], b[0][2], b[0][3], bAddr0 + boff);
            ldsm4(b[1][0], b[1][1], b[1][2], b[1][3], bAddr1 + boff);
#pragma unroll
            for (int m = 0; m < 4; m++) {
                mma16816(acc[m][0][0], acc[m][0][1], acc[m][0][2], acc[m][0][3],
                         a[m][0], a[m][1], a[m][2], a[m][3], b[0][0], b[0][1]);
                mma16816(acc[m][1][0], acc[m][1][1], acc[m][1][2], acc[m][1][3],
                         a[m][0], a[m][1], a[m][2], a[m][3], b[0][2], b[0][3]);
                mma16816(acc[m][2][0], acc[m][2][1], acc[m][2][2], acc[m][2][3],
                         a[m][0], a[m][1], a[m][2], a[m][3], b[1][0], b[1][1]);
                mma16816(acc[m][3][0], acc[m][3][1], acc[m][3][2], acc[m][3][3],
                         a[m][0], a[m][1], a[m][2], a[m][3], b[1][2], b[1][3]);
            }
        }

        // epilogue: fold tile into (maxAll, maxBelow)
#pragma unroll
        for (int n = 0; n < 4; n++) {
            int s0 = sv[n][0], s1 = sv[n][1];
#pragma unroll
            for (int m = 0; m < 4; m++) {
#pragma unroll
                for (int h = 0; h < 2; h++) {
                    int slot = 2 * m + h;
                    float hpv = hp_s[slot];
                    int mp = pid_s[slot];
                    float v0 = acc[m][n][h * 2 + 0];
                    float v1 = acc[m][n][h * 2 + 1];
                    bool k0 = (s0 == mp), k1 = (s1 == mp);
                    float a0 = k0 ? -1e9f : v0;
                    float a1 = k1 ? -1e9f : v1;
                    mA[slot] = fmaxf(mA[slot], fmaxf(a0, a1));
                    float b0 = (k0 || v0 >= hpv) ? -1e9f : v0;
                    float b1 = (k1 || v1 >= hpv) ? -1e9f : v1;
                    mB[slot] = fmaxf(mB[slot], fmaxf(b0, b1));
                }
            }
        }
    }

#pragma unroll
    for (int s = 0; s < 8; s++)
        for (int o = 1; o < 4; o <<= 1) {
            mA[s] = fmaxf(mA[s], __shfl_xor_sync(0xffffffffu, mA[s], o));
            mB[s] = fmaxf(mB[s], __shfl_xor_sync(0xffffffffu, mB[s], o));
        }
    if (tig == 0) {
#pragma unroll
        for (int m = 0; m < 4; m++) {
            int r = row0 + wr + m * 16 + gid;
            atomicMax(&g_aE[r], encf(mA[2 * m]));
            atomicMax(&g_bE[r], encf(mB[2 * m]));
            atomicMax(&g_aE[r + 8], encf(mA[2 * m + 1]));
            atomicMax(&g_bE[r + 8], encf(mB[2 * m + 1]));
        }
    }
}

// ---------------- final reduce ----------------
__global__ void finish_k(float* __restrict__ out) {
    float s = 0.f, c = 0.f;
    for (int i = threadIdx.x; i < N_; i += blockDim.x) {
        if (g_validf[i] > 0.f) {
            float hp = g_hp[i];
            float maxA = decf(g_aE[i]);
            float maxB = decf(g_bE[i]);
            float hn = (maxB > hp - 0.5f) ? maxB : maxA;
            float base = fmaxf(hn - hp + 0.5f, 0.f);
            float w = (hp < 0.6f || hn > 0.3f) ? 2.0f : 1.0f;
            s += base * w + 0.5f * (1.0f - hp) + 0.5f * fmaxf(hn + 0.2f, 0.f);
            c += 1.f;
        }
    }
    __shared__ float rs[32], rc[32];
    for (int o = 16; o; o >>= 1) {
        s += __shfl_xor_sync(0xffffffffu, s, o);
        c += __shfl_xor_sync(0xffffffffu, c, o);
    }
    int wid = threadIdx.x >> 5, lane = threadIdx.x & 31;
    if (lane == 0) { rs[wid] = s; rc[wid] = c; }
    __syncthreads();
    int nw = (blockDim.x + 31) >> 5;
    if (wid == 0) {
        float vs = lane < nw ? rs[lane] : 0.f;
        float vc = lane < nw ? rc[lane] : 0.f;
        for (int o = 16; o; o >>= 1) {
            vs += __shfl_xor_sync(0xffffffffu, vs, o);
            vc += __shfl_xor_sync(0xffffffffu, vc, o);
        }
        if (lane == 0) out[0] = (vc > 0.f) ? (vs / vc) : 0.f;
    }
}

// ---------------- launcher ----------------
extern "C" void kernel_launch(void* const* d_in, const int* in_sizes, int n_in,
                              void* d_out, int out_size) {
    const float* emb = (const float*)d_in[0];
    const int* labels = (const int*)d_in[1];
    const int* pids = (const int*)d_in[2];
    float* out = (float*)d_out;

    cudaFuncSetAttribute(main_k, cudaFuncAttributeMaxDynamicSharedMemorySize, 196608);
    cudaFuncSetAttribute(hp_pid_k, cudaFuncAttributeMaxDynamicSharedMemorySize, 65536);

    zero_k<<<1, 256>>>();
    normalize_k<<<N_, 64>>>(emb, labels, pids);
    hp_pid_k<<<NPID, 256, 65536>>>();
    main_k<<<dim3(64, 2), 256, 196608>>>(pids);
    finish_k<<<1, 1024>>>(out);
}

// round 8
// speedup vs baseline: 1.0832x; 1.0832x over previous
#include <cuda_runtime.h>
#include <cuda_fp16.h>
#include <cstdint>
#include <math.h>

#define N_    8192
#define D_    256
#define NPID  256
#define CAP   8192
#define NTILE 32

__device__ float    g_normed[N_ * D_];
__device__ __half   g_nh[N_ * D_];
__device__ float    g_hp[N_];
__device__ float    g_validf[N_];
__device__ int      g_colsent[N_];
__device__ int      g_cnt[NPID];
__device__ int      g_list[NPID * CAP];
__device__ unsigned g_aE[N_];   // encoded max over masked negatives (all)
__device__ unsigned g_bE[N_];   // encoded max over masked negatives with v < hp

__device__ __forceinline__ unsigned encf(float f) {
    unsigned u = __float_as_uint(f);
    return (u & 0x80000000u) ? ~u : (u | 0x80000000u);
}
__device__ __forceinline__ float decf(unsigned e) {
    unsigned u = (e & 0x80000000u) ? (e ^ 0x80000000u) : ~e;
    return __uint_as_float(u);
}
__device__ __forceinline__ uint32_t smem_u32(const void* p) {
    uint32_t a;
    asm("{ .reg .u64 t; cvta.to.shared.u64 t, %1; cvt.u32.u64 %0, t; }" : "=r"(a) : "l"(p));
    return a;
}
__device__ __forceinline__ void cpa16(uint32_t d, const void* s) {
    asm volatile("cp.async.cg.shared.global [%0], [%1], 16;" :: "r"(d), "l"(s) : "memory");
}
#define CP_COMMIT() asm volatile("cp.async.commit_group;" ::: "memory")
#define CP_WAIT(n)  asm volatile("cp.async.wait_group %0;" :: "n"(n) : "memory")

__device__ __forceinline__ void ldsm4(uint32_t& r0, uint32_t& r1, uint32_t& r2, uint32_t& r3,
                                      uint32_t addr) {
    asm volatile("ldmatrix.sync.aligned.m8n8.x4.shared.b16 {%0,%1,%2,%3}, [%4];"
                 : "=r"(r0), "=r"(r1), "=r"(r2), "=r"(r3) : "r"(addr));
}
__device__ __forceinline__ void mma16816(float& c0, float& c1, float& c2, float& c3,
                                         uint32_t a0, uint32_t a1, uint32_t a2, uint32_t a3,
                                         uint32_t b0, uint32_t b1) {
    asm volatile("mma.sync.aligned.m16n8k16.row.col.f32.f16.f16.f32 "
                 "{%0,%1,%2,%3},{%4,%5,%6,%7},{%8,%9},{%0,%1,%2,%3};"
                 : "+f"(c0), "+f"(c1), "+f"(c2), "+f"(c3)
                 : "r"(a0), "r"(a1), "r"(a2), "r"(a3), "r"(b0), "r"(b1));
}

// ---------------- normalize + fp16 copy + bucket + init ----------------
__global__ void normalize_k(const float* __restrict__ emb,
                            const int* __restrict__ labels,
                            const int* __restrict__ pids) {
    int j = blockIdx.x, t = threadIdx.x;  // 64 threads, one float4 each
    float4 v = ((const float4*)(emb + (size_t)j * D_))[t];
    float ss = v.x * v.x + v.y * v.y + v.z * v.z + v.w * v.w;
    for (int o = 16; o; o >>= 1) ss += __shfl_xor_sync(0xffffffffu, ss, o);
    __shared__ float sred[2];
    if ((t & 31) == 0) sred[t >> 5] = ss;
    __syncthreads();
    float inv = 1.0f / fmaxf(sqrtf(sred[0] + sred[1]), 1e-12f);
    float4 o4 = make_float4(v.x * inv, v.y * inv, v.z * inv, v.w * inv);
    ((float4*)(g_normed + (size_t)j * D_))[t] = o4;
    __half2 h0 = __floats2half2_rn(o4.x, o4.y);
    __half2 h1 = __floats2half2_rn(o4.z, o4.w);
    ((__half2*)(g_nh + (size_t)j * D_ + t * 4))[0] = h0;
    ((__half2*)(g_nh + (size_t)j * D_ + t * 4))[1] = h1;
    if (t == 0) {
        g_hp[j] = 1e9f;
        g_validf[j] = 0.f;
        unsigned e = encf(-1e9f);
        g_aE[j] = e;
        g_bE[j] = e;
        int lab = labels[j], pid = pids[j];
        g_colsent[j] = (lab == 1) ? pid : -1;
        if (lab == 1) g_list[pid * CAP + atomicAdd(&g_cnt[pid], 1)] = j;
    }
}

__global__ void zero_k() { if (threadIdx.x < NPID) g_cnt[threadIdx.x] = 0; }

// ---------------- hardest positive: block per pid, smem-staged ----------------
__global__ void __launch_bounds__(256, 1)
hp_pid_k() {
    extern __shared__ float srow[];  // up to 64 rows x 256 floats
    int p = blockIdx.x;
    int n = g_cnt[p];
    if (n == 0) return;
    int ns = (n < 64) ? n : 64;
    for (int idx = threadIdx.x; idx < ns * 64; idx += 256) {
        int m = idx >> 6, q = idx & 63;
        ((float4*)srow)[m * 64 + q] =
            ((const float4*)(g_normed + (size_t)g_list[p * CAP + m] * D_))[q];
    }
    __syncthreads();
    int wid = threadIdx.x >> 5, lane = threadIdx.x & 31;
    float vf = (n >= 2) ? 1.f : 0.f;
    for (int a = wid; a < n; a += 8) {
        int i = g_list[p * CAP + a];
        const float* arow = (a < ns) ? (srow + a * D_) : (g_normed + (size_t)i * D_);
        float a8[8];
#pragma unroll
        for (int k = 0; k < 8; k++) a8[k] = arow[k * 32 + lane];
        float hp = 1e9f;
        for (int j = 0; j < n; j++) {
            if (j == a) continue;
            const float* br = (j < ns) ? (srow + j * D_)
                                       : (g_normed + (size_t)g_list[p * CAP + j] * D_);
            float s = 0.f;
#pragma unroll
            for (int k = 0; k < 8; k++) s = fmaf(a8[k], br[k * 32 + lane], s);
            for (int o = 16; o; o >>= 1) s += __shfl_xor_sync(0xffffffffu, s, o);
            hp = fminf(hp, s);
        }
        if (lane == 0) { g_hp[i] = hp; g_validf[i] = vf; }
    }
}

// ---------------- main: 512 threads, 16 warps, warp tile 32x32 ----------------
__global__ void __launch_bounds__(512, 1)
main_k(const int* __restrict__ pids) {
    extern __shared__ char sm[];
    uint32_t sb = smem_u32(sm);
    const uint32_t A0 = sb, Bbuf0 = sb + 65536, Bbuf1 = sb + 131072;

    int tid = threadIdx.x, lane = tid & 31, wid = tid >> 5;
    int wr = (wid >> 2) * 32;   // 4 row groups of 32
    int wc = (wid & 3) * 32;    // 4 col groups of 32
    int row0 = blockIdx.x * 128;
    int col0 = blockIdx.y * 4096;

    {
        const __half* gs = g_nh + (size_t)row0 * D_;
#pragma unroll
        for (int i = 0; i < 8; i++) {
            int id = tid + i * 512, r = id >> 5, c = id & 31;
            cpa16(A0 + r * 512 + ((c ^ (r & 7)) << 4), gs + r * 256 + c * 8);
        }
        const __half* gb = g_nh + (size_t)col0 * D_;
#pragma unroll
        for (int i = 0; i < 8; i++) {
            int id = tid + i * 512, r = id >> 5, c = id & 31;
            cpa16(Bbuf0 + r * 512 + ((c ^ (r & 7)) << 4), gb + r * 256 + c * 8);
        }
        CP_COMMIT();
    }

    int gid = lane >> 2, tig = lane & 3;
    float hp_s[4], mA[4], mB[4];
    int pid_s[4];
#pragma unroll
    for (int m = 0; m < 2; m++) {
        int rA = row0 + wr + m * 16 + gid;
        hp_s[2 * m] = g_hp[rA];         pid_s[2 * m] = pids[rA];
        hp_s[2 * m + 1] = g_hp[rA + 8]; pid_s[2 * m + 1] = pids[rA + 8];
    }
#pragma unroll
    for (int s = 0; s < 4; s++) { mA[s] = -1e9f; mB[s] = -1e9f; }

    int arow = lane & 15;
    int kha = lane >> 4;
    int brow = ((lane >> 4) & 1) * 8 + (lane & 7);
    int khb = (lane >> 3) & 1;
    int xr = lane & 7;
    uint32_t aAddr[2];
#pragma unroll
    for (int m = 0; m < 2; m++) aAddr[m] = A0 + (wr + m * 16 + arow) * 512;

    for (int t = 0; t < NTILE; t++) {
        uint32_t Bc = (t & 1) ? Bbuf1 : Bbuf0;
        if (t + 1 < NTILE) {   // issue prefetch BEFORE waiting (R6 ordering)
            uint32_t Bn = (t & 1) ? Bbuf0 : Bbuf1;
            const __half* gs = g_nh + (size_t)(col0 + (t + 1) * 128) * D_;
#pragma unroll
            for (int i = 0; i < 8; i++) {
                int id = tid + i * 512, r = id >> 5, c = id & 31;
                cpa16(Bn + r * 512 + ((c ^ (r & 7)) << 4), gs + r * 256 + c * 8);
            }
            CP_COMMIT();
            CP_WAIT(1);
        } else {
            CP_WAIT(0);
        }
        __syncthreads();

        // preload epilogue sentinels (hidden behind mma loop)
        int cb = col0 + t * 128 + wc;
        int sv[4][2];
#pragma unroll
        for (int n = 0; n < 4; n++) {
            sv[n][0] = __ldg(&g_colsent[cb + n * 8 + tig * 2]);
            sv[n][1] = __ldg(&g_colsent[cb + n * 8 + tig * 2 + 1]);
        }

        uint32_t bAddr0 = Bc + (wc + brow) * 512;
        uint32_t bAddr1 = Bc + (wc + 16 + brow) * 512;

        float acc[2][4][4];
#pragma unroll
        for (int m = 0; m < 2; m++)
#pragma unroll
            for (int n = 0; n < 4; n++)
#pragma unroll
                for (int q = 0; q < 4; q++) acc[m][n][q] = 0.f;

#pragma unroll
        for (int ks = 0; ks < 16; ks++) {
            uint32_t aoff = (uint32_t)(((ks * 2 + kha) ^ xr) << 4);
            uint32_t boff = (uint32_t)(((ks * 2 + khb) ^ xr) << 4);
            uint32_t a[2][4], b[2][4];
#pragma unroll
            for (int m = 0; m < 2; m++)
                ldsm4(a[m][0], a[m][1], a[m][2], a[m][3], aAddr[m] + aoff);
            ldsm4(b[0][0], b[0][1], b[0][2], b[0][3], bAddr0 + boff);
            ldsm4(b[1][0], b[1][1], b[1][2], b[1][3], bAddr1 + boff);
#pragma unroll
            for (int m = 0; m < 2; m++) {
                mma16816(acc[m][0][0], acc[m][0][1], acc[m][0][2], acc[m][0][3],
                         a[m][0], a[m][1], a[m][2], a[m][3], b[0][0], b[0][1]);
                mma16816(acc[m][1][0], acc[m][1][1], acc[m][1][2], acc[m][1][3],
                         a[m][0], a[m][1], a[m][2], a[m][3], b[0][2], b[0][3]);
                mma16816(acc[m][2][0], acc[m][2][1], acc[m][2][2], acc[m][2][3],
                         a[m][0], a[m][1], a[m][2], a[m][3], b[1][0], b[1][1]);
                mma16816(acc[m][3][0], acc[m][3][1], acc[m][3][2], acc[m][3][3],
                         a[m][0], a[m][1], a[m][2], a[m][3], b[1][2], b[1][3]);
            }
        }

        // epilogue: fold tile into (maxAll, maxBelow)
#pragma unroll
        for (int n = 0; n < 4; n++) {
            int s0 = sv[n][0], s1 = sv[n][1];
#pragma unroll
            for (int m = 0; m < 2; m++) {
#pragma unroll
                for (int h = 0; h < 2; h++) {
                    int slot = 2 * m + h;
                    float hpv = hp_s[slot];
                    int mp = pid_s[slot];
                    float v0 = acc[m][n][h * 2 + 0];
                    float v1 = acc[m][n][h * 2 + 1];
                    bool k0 = (s0 == mp), k1 = (s1 == mp);
                    float a0 = k0 ? -1e9f : v0;
                    float a1 = k1 ? -1e9f : v1;
                    mA[slot] = fmaxf(mA[slot], fmaxf(a0, a1));
                    float b0 = (k0 || v0 >= hpv) ? -1e9f : v0;
                    float b1 = (k1 || v1 >= hpv) ? -1e9f : v1;
                    mB[slot] = fmaxf(mB[slot], fmaxf(b0, b1));
                }
            }
        }
        __syncthreads();  // guards buffer reuse by next prefetch
    }

#pragma unroll
    for (int s = 0; s < 4; s++)
        for (int o = 1; o < 4; o <<= 1) {
            mA[s] = fmaxf(mA[s], __shfl_xor_sync(0xffffffffu, mA[s], o));
            mB[s] = fmaxf(mB[s], __shfl_xor_sync(0xffffffffu, mB[s], o));
        }
    if (tig == 0) {
#pragma unroll
        for (int m = 0; m < 2; m++) {
            int r = row0 + wr + m * 16 + gid;
            atomicMax(&g_aE[r], encf(mA[2 * m]));
            atomicMax(&g_bE[r], encf(mB[2 * m]));
            atomicMax(&g_aE[r + 8], encf(mA[2 * m + 1]));
            atomicMax(&g_bE[r + 8], encf(mB[2 * m + 1]));
        }
    }
}

// ---------------- final reduce ----------------
__global__ void finish_k(float* __restrict__ out) {
    float s = 0.f, c = 0.f;
    for (int i = threadIdx.x; i < N_; i += blockDim.x) {
        if (g_validf[i] > 0.f) {
            float hp = g_hp[i];
            float maxA = decf(g_aE[i]);
            float maxB = decf(g_bE[i]);
            float hn = (maxB > hp - 0.5f) ? maxB : maxA;
            float base = fmaxf(hn - hp + 0.5f, 0.f);
            float w = (hp < 0.6f || hn > 0.3f) ? 2.0f : 1.0f;
            s += base * w + 0.5f * (1.0f - hp) + 0.5f * fmaxf(hn + 0.2f, 0.f);
            c += 1.f;
        }
    }
    __shared__ float rs[32], rc[32];
    for (int o = 16; o; o >>= 1) {
        s += __shfl_xor_sync(0xffffffffu, s, o);
        c += __shfl_xor_sync(0xffffffffu, c, o);
    }
    int wid = threadIdx.x >> 5, lane = threadIdx.x & 31;
    if (lane == 0) { rs[wid] = s; rc[wid] = c; }
    __syncthreads();
    int nw = (blockDim.x + 31) >> 5;
    if (wid == 0) {
        float vs = lane < nw ? rs[lane] : 0.f;
        float vc = lane < nw ? rc[lane] : 0.f;
        for (int o = 16; o; o >>= 1) {
            vs += __shfl_xor_sync(0xffffffffu, vs, o);
            vc += __shfl_xor_sync(0xffffffffu, vc, o);
        }
        if (lane == 0) out[0] = (vc > 0.f) ? (vs / vc) : 0.f;
    }
}

// ---------------- launcher ----------------
extern "C" void kernel_launch(void* const* d_in, const int* in_sizes, int n_in,
                              void* d_out, int out_size) {
    const float* emb = (const float*)d_in[0];
    const int* labels = (const int*)d_in[1];
    const int* pids = (const int*)d_in[2];
    float* out = (float*)d_out;

    cudaFuncSetAttribute(main_k, cudaFuncAttributeMaxDynamicSharedMemorySize, 196608);
    cudaFuncSetAttribute(hp_pid_k, cudaFuncAttributeMaxDynamicSharedMemorySize, 65536);

    zero_k<<<1, 256>>>();
    normalize_k<<<N_, 64>>>(emb, labels, pids);
    hp_pid_k<<<NPID, 256, 65536>>>();
    main_k<<<dim3(64, 2), 512, 196608>>>(pids);
    finish_k<<<1, 1024>>>(out);
}

// round 9
// speedup vs baseline: 1.2819x; 1.1834x over previous
#include <cuda_runtime.h>
#include <cuda_fp16.h>
#include <cstdint>
#include <math.h>

#define N_    8192
#define D_    256
#define NPID  256
#define NB    64          // 128-row blocks
#define TT    2080        // NB*(NB+1)/2 triangle tiles
#define NCTA  148

__device__ float    g_normed[N_ * D_];
__device__ __half   g_nh[N_ * D_];
__device__ float    g_hp[N_];
__device__ float    g_validf[N_];
__device__ int      g_colsent[N_];
__device__ unsigned g_aE[N_];   // encoded max over masked negatives (all)
__device__ unsigned g_bE[N_];   // encoded max over masked negatives with v < hp

__device__ __forceinline__ unsigned encf(float f) {
    unsigned u = __float_as_uint(f);
    return (u & 0x80000000u) ? ~u : (u | 0x80000000u);
}
__device__ __forceinline__ float decf(unsigned e) {
    unsigned u = (e & 0x80000000u) ? (e ^ 0x80000000u) : ~e;
    return __uint_as_float(u);
}
__device__ __forceinline__ uint32_t smem_u32(const void* p) {
    uint32_t a;
    asm("{ .reg .u64 t; cvta.to.shared.u64 t, %1; cvt.u32.u64 %0, t; }" : "=r"(a) : "l"(p));
    return a;
}
__device__ __forceinline__ void cpa16(uint32_t d, const void* s) {
    asm volatile("cp.async.cg.shared.global [%0], [%1], 16;" :: "r"(d), "l"(s) : "memory");
}
#define CP_COMMIT() asm volatile("cp.async.commit_group;" ::: "memory")
#define CP_WAIT(n)  asm volatile("cp.async.wait_group %0;" :: "n"(n) : "memory")

__device__ __forceinline__ void ldsm4(uint32_t& r0, uint32_t& r1, uint32_t& r2, uint32_t& r3,
                                      uint32_t addr) {
    asm volatile("ldmatrix.sync.aligned.m8n8.x4.shared.b16 {%0,%1,%2,%3}, [%4];"
                 : "=r"(r0), "=r"(r1), "=r"(r2), "=r"(r3) : "r"(addr));
}
__device__ __forceinline__ void mma16816(float& c0, float& c1, float& c2, float& c3,
                                         uint32_t a0, uint32_t a1, uint32_t a2, uint32_t a3,
                                         uint32_t b0, uint32_t b1) {
    asm volatile("mma.sync.aligned.m16n8k16.row.col.f32.f16.f16.f32 "
                 "{%0,%1,%2,%3},{%4,%5,%6,%7},{%8,%9},{%0,%1,%2,%3};"
                 : "+f"(c0), "+f"(c1), "+f"(c2), "+f"(c3)
                 : "r"(a0), "r"(a1), "r"(a2), "r"(a3), "r"(b0), "r"(b1));
}

// linear triangle index -> (bi, bj), bj <= bi
__device__ __forceinline__ void dec_tri(int k, int& bi, int& bj) {
    int b = (int)((sqrtf(8.f * (float)k + 1.f) - 1.f) * 0.5f);
    while ((b + 1) * (b + 2) / 2 <= k) b++;
    while (b * (b + 1) / 2 > k) b--;
    bi = b;
    bj = k - b * (b + 1) / 2;
}

// ---------------- normalize + fp16 copy + sentinels + init ----------------
__global__ void normalize_k(const float* __restrict__ emb,
                            const int* __restrict__ labels,
                            const int* __restrict__ pids) {
    int j = blockIdx.x, t = threadIdx.x;  // 64 threads, one float4 each
    float4 v = ((const float4*)(emb + (size_t)j * D_))[t];
    float ss = v.x * v.x + v.y * v.y + v.z * v.z + v.w * v.w;
    for (int o = 16; o; o >>= 1) ss += __shfl_xor_sync(0xffffffffu, ss, o);
    __shared__ float sred[2];
    if ((t & 31) == 0) sred[t >> 5] = ss;
    __syncthreads();
    float inv = 1.0f / fmaxf(sqrtf(sred[0] + sred[1]), 1e-12f);
    float4 o4 = make_float4(v.x * inv, v.y * inv, v.z * inv, v.w * inv);
    ((float4*)(g_normed + (size_t)j * D_))[t] = o4;
    __half2 h0 = __floats2half2_rn(o4.x, o4.y);
    __half2 h1 = __floats2half2_rn(o4.z, o4.w);
    ((__half2*)(g_nh + (size_t)j * D_ + t * 4))[0] = h0;
    ((__half2*)(g_nh + (size_t)j * D_ + t * 4))[1] = h1;
    if (t == 0) {
        g_hp[j] = 1e9f;
        g_validf[j] = 0.f;
        unsigned e = encf(-1e9f);
        g_aE[j] = e;
        g_bE[j] = e;
        g_colsent[j] = (labels[j] == 1) ? pids[j] : -1;
    }
}

// ------------- hardest positive: block per pid, scan + smem stage -------------
__global__ void __launch_bounds__(256, 1)
hp_pid_k(const int* __restrict__ labels, const int* __restrict__ pids) {
    extern __shared__ float srow[];                 // 64 rows x 256 floats
    __shared__ int slist[1024];
    __shared__ int sn;
    int p = blockIdx.x;
    if (threadIdx.x == 0) sn = 0;
    __syncthreads();
    for (int j = threadIdx.x; j < N_; j += 256)
        if (pids[j] == p && labels[j] == 1) {
            int q = atomicAdd(&sn, 1);
            if (q < 1024) slist[q] = j;
        }
    __syncthreads();
    int n = sn < 1024 ? sn : 1024;
    if (n == 0) return;
    int ns = (n < 64) ? n : 64;
    for (int idx = threadIdx.x; idx < ns * 64; idx += 256) {
        int m = idx >> 6, q = idx & 63;
        ((float4*)srow)[m * 64 + q] =
            ((const float4*)(g_normed + (size_t)slist[m] * D_))[q];
    }
    __syncthreads();
    int wid = threadIdx.x >> 5, lane = threadIdx.x & 31;
    float vf = (n >= 2) ? 1.f : 0.f;
    for (int a = wid; a < n; a += 8) {
        int i = slist[a];
        const float* arow = (a < ns) ? (srow + a * D_) : (g_normed + (size_t)i * D_);
        float a8[8];
#pragma unroll
        for (int k = 0; k < 8; k++) a8[k] = arow[k * 32 + lane];
        float hp = 1e9f;
        for (int j = 0; j < n; j++) {
            if (j == a) continue;
            const float* br = (j < ns) ? (srow + j * D_)
                                       : (g_normed + (size_t)slist[j] * D_);
            float s = 0.f;
#pragma unroll
            for (int k = 0; k < 8; k++) s = fmaf(a8[k], br[k * 32 + lane], s);
            for (int o = 16; o; o >>= 1) s += __shfl_xor_sync(0xffffffffu, s, o);
            hp = fminf(hp, s);
        }
        if (lane == 0) { g_hp[i] = hp; g_validf[i] = vf; }
    }
}

// -------- main: triangular mma.sync GEMM, row+column dual fold --------
__global__ void __launch_bounds__(512, 1)
main_k(const int* __restrict__ pids) {
    extern __shared__ char sm[];
    uint32_t sb = smem_u32(sm);
    const uint32_t A0 = sb, Bbuf0 = sb + 65536, Bbuf1 = sb + 131072;

    int tid = threadIdx.x, lane = tid & 31, wid = tid >> 5;
    int wr = (wid >> 2) * 32;
    int wc = (wid & 3) * 32;
    int gid = lane >> 2, tig = lane & 3;

    int k0 = (int)(((long long)blockIdx.x * TT) / NCTA);
    int k1 = (int)(((long long)(blockIdx.x + 1) * TT) / NCTA);
    if (k0 >= k1) return;

    int bi0, bj0;
    dec_tri(k0, bi0, bj0);

    // initial A(bi0) + B(bj0) load, one group
    {
        const __half* ga = g_nh + (size_t)bi0 * 128 * D_;
#pragma unroll
        for (int i = 0; i < 8; i++) {
            int id = tid + i * 512, r = id >> 5, c = id & 31;
            cpa16(A0 + r * 512 + ((c ^ (r & 7)) << 4), ga + r * 256 + c * 8);
        }
        const __half* gb = g_nh + (size_t)bj0 * 128 * D_;
#pragma unroll
        for (int i = 0; i < 8; i++) {
            int id = tid + i * 512, r = id >> 5, c = id & 31;
            cpa16(Bbuf0 + r * 512 + ((c ^ (r & 7)) << 4), gb + r * 256 + c * 8);
        }
        CP_COMMIT();
    }

    // per-bi row-anchor state
    float hp_s[4], mA[4], mB[4];
    int pid_s[4], rsent[4];
    int cur_bi = bi0;
    {
#pragma unroll
        for (int m = 0; m < 2; m++) {
            int rA = bi0 * 128 + wr + m * 16 + gid;
            hp_s[2 * m] = g_hp[rA];         pid_s[2 * m] = pids[rA];     rsent[2 * m] = g_colsent[rA];
            hp_s[2 * m + 1] = g_hp[rA + 8]; pid_s[2 * m + 1] = pids[rA + 8]; rsent[2 * m + 1] = g_colsent[rA + 8];
        }
#pragma unroll
        for (int s = 0; s < 4; s++) { mA[s] = -1e9f; mB[s] = -1e9f; }
    }

    int arow = lane & 15;
    int kha = lane >> 4;
    int brow = ((lane >> 4) & 1) * 8 + (lane & 7);
    int khb = (lane >> 3) & 1;
    int xr = lane & 7;
    uint32_t aAddr[2];
#pragma unroll
    for (int m = 0; m < 2; m++) aAddr[m] = A0 + (wr + m * 16 + arow) * 512;

    for (int k = k0; k < k1; k++) {
        int bi, bj;
        dec_tri(k, bi, bj);

        // A change: flush row maxes of cur_bi, start A(bi) load, reload row state
        if (bi != cur_bi) {
#pragma unroll
            for (int s = 0; s < 4; s++) {
                float a = mA[s], b = mB[s];
                for (int o = 1; o < 4; o <<= 1) {
                    a = fmaxf(a, __shfl_xor_sync(0xffffffffu, a, o));
                    b = fmaxf(b, __shfl_xor_sync(0xffffffffu, b, o));
                }
                if (tig == 0) {
                    int r = cur_bi * 128 + wr + (s >> 1) * 16 + (s & 1) * 8 + gid;
                    atomicMax(&g_aE[r], encf(a));
                    atomicMax(&g_bE[r], encf(b));
                }
                mA[s] = -1e9f; mB[s] = -1e9f;
            }
            const __half* ga = g_nh + (size_t)bi * 128 * D_;
#pragma unroll
            for (int i = 0; i < 8; i++) {
                int id = tid + i * 512, r = id >> 5, c = id & 31;
                cpa16(A0 + r * 512 + ((c ^ (r & 7)) << 4), ga + r * 256 + c * 8);
            }
            CP_COMMIT();
#pragma unroll
            for (int m = 0; m < 2; m++) {
                int rA = bi * 128 + wr + m * 16 + gid;
                hp_s[2 * m] = g_hp[rA];         pid_s[2 * m] = pids[rA];     rsent[2 * m] = g_colsent[rA];
                hp_s[2 * m + 1] = g_hp[rA + 8]; pid_s[2 * m + 1] = pids[rA + 8]; rsent[2 * m + 1] = g_colsent[rA + 8];
            }
            cur_bi = bi;
        }

        int pb = (k - k0) & 1;
        uint32_t Bc = pb ? Bbuf1 : Bbuf0;

        if (k + 1 < k1) {   // prefetch next B (before waiting — proven ordering)
            int nbi, nbj;
            dec_tri(k + 1, nbi, nbj);
            uint32_t Bn = pb ? Bbuf0 : Bbuf1;
            const __half* gs = g_nh + (size_t)nbj * 128 * D_;
#pragma unroll
            for (int i = 0; i < 8; i++) {
                int id = tid + i * 512, r = id >> 5, c = id & 31;
                cpa16(Bn + r * 512 + ((c ^ (r & 7)) << 4), gs + r * 256 + c * 8);
            }
            CP_COMMIT();
            CP_WAIT(1);
        } else {
            CP_WAIT(0);
        }
        __syncthreads();

        // per-tile column-side values (latency hidden behind mma)
        int cbase = bj * 128 + wc;
        int sv[4][2], pidc[4][2];
        float hpc[4][2];
#pragma unroll
        for (int n = 0; n < 4; n++) {
#pragma unroll
            for (int c = 0; c < 2; c++) {
                int cg = cbase + n * 8 + tig * 2 + c;
                sv[n][c] = __ldg(&g_colsent[cg]);
                pidc[n][c] = __ldg(&pids[cg]);
                hpc[n][c] = __ldg(&g_hp[cg]);
            }
        }

        uint32_t bAddr0 = Bc + (wc + brow) * 512;
        uint32_t bAddr1 = Bc + (wc + 16 + brow) * 512;

        float acc[2][4][4];
#pragma unroll
        for (int m = 0; m < 2; m++)
#pragma unroll
            for (int n = 0; n < 4; n++)
#pragma unroll
                for (int q = 0; q < 4; q++) acc[m][n][q] = 0.f;

#pragma unroll
        for (int ks = 0; ks < 16; ks++) {
            uint32_t aoff = (uint32_t)(((ks * 2 + kha) ^ xr) << 4);
            uint32_t boff = (uint32_t)(((ks * 2 + khb) ^ xr) << 4);
            uint32_t a[2][4], b[2][4];
#pragma unroll
            for (int m = 0; m < 2; m++)
                ldsm4(a[m][0], a[m][1], a[m][2], a[m][3], aAddr[m] + aoff);
            ldsm4(b[0][0], b[0][1], b[0][2], b[0][3], bAddr0 + boff);
            ldsm4(b[1][0], b[1][1], b[1][2], b[1][3], bAddr1 + boff);
#pragma unroll
            for (int m = 0; m < 2; m++) {
                mma16816(acc[m][0][0], acc[m][0][1], acc[m][0][2], acc[m][0][3],
                         a[m][0], a[m][1], a[m][2], a[m][3], b[0][0], b[0][1]);
                mma16816(acc[m][1][0], acc[m][1][1], acc[m][1][2], acc[m][1][3],
                         a[m][0], a[m][1], a[m][2], a[m][3], b[0][2], b[0][3]);
                mma16816(acc[m][2][0], acc[m][2][1], acc[m][2][2], acc[m][2][3],
                         a[m][0], a[m][1], a[m][2], a[m][3], b[1][0], b[1][1]);
                mma16816(acc[m][3][0], acc[m][3][1], acc[m][3][2], acc[m][3][3],
                         a[m][0], a[m][1], a[m][2], a[m][3], b[1][2], b[1][3]);
            }
        }

        // --- row-anchor fold (anchors = rows of bi block) ---
#pragma unroll
        for (int n = 0; n < 4; n++) {
#pragma unroll
            for (int m = 0; m < 2; m++) {
#pragma unroll
                for (int h = 0; h < 2; h++) {
                    int slot = 2 * m + h;
                    float hpv = hp_s[slot];
                    int mp = pid_s[slot];
                    float v0 = acc[m][n][h * 2 + 0];
                    float v1 = acc[m][n][h * 2 + 1];
                    bool c0k = (sv[n][0] == mp), c1k = (sv[n][1] == mp);
                    float a0 = c0k ? -1e9f : v0;
                    float a1 = c1k ? -1e9f : v1;
                    mA[slot] = fmaxf(mA[slot], fmaxf(a0, a1));
                    float b0 = (c0k || v0 >= hpv) ? -1e9f : v0;
                    float b1 = (c1k || v1 >= hpv) ? -1e9f : v1;
                    mB[slot] = fmaxf(mB[slot], fmaxf(b0, b1));
                }
            }
        }

        // --- column-anchor fold (anchors = cols of bj block, candidates = rows) ---
#pragma unroll
        for (int n = 0; n < 4; n++) {
#pragma unroll
            for (int c = 0; c < 2; c++) {
                int pj = pidc[n][c];
                float hpj = hpc[n][c];
                float cA = -1e9f, cB = -1e9f;
#pragma unroll
                for (int m = 0; m < 2; m++) {
#pragma unroll
                    for (int h = 0; h < 2; h++) {
                        float v = acc[m][n][h * 2 + c];
                        bool kill = (rsent[2 * m + h] == pj);
                        cA = fmaxf(cA, kill ? -1e9f : v);
                        cB = fmaxf(cB, (kill || v >= hpj) ? -1e9f : v);
                    }
                }
                for (int o = 4; o < 32; o <<= 1) {
                    cA = fmaxf(cA, __shfl_xor_sync(0xffffffffu, cA, o));
                    cB = fmaxf(cB, __shfl_xor_sync(0xffffffffu, cB, o));
                }
                if (gid == 0) {
                    int cg = cbase + n * 8 + tig * 2 + c;
                    atomicMax(&g_aE[cg], encf(cA));
                    atomicMax(&g_bE[cg], encf(cB));
                }
            }
        }
        __syncthreads();  // all threads done with Bc/A0 before next prefetch/A-load
    }

    // final flush of row maxes
#pragma unroll
    for (int s = 0; s < 4; s++) {
        float a = mA[s], b = mB[s];
        for (int o = 1; o < 4; o <<= 1) {
            a = fmaxf(a, __shfl_xor_sync(0xffffffffu, a, o));
            b = fmaxf(b, __shfl_xor_sync(0xffffffffu, b, o));
        }
        if (tig == 0) {
            int r = cur_bi * 128 + wr + (s >> 1) * 16 + (s & 1) * 8 + gid;
            atomicMax(&g_aE[r], encf(a));
            atomicMax(&g_bE[r], encf(b));
        }
    }
}

// ---------------- final reduce ----------------
__global__ void finish_k(float* __restrict__ out) {
    float s = 0.f, c = 0.f;
    for (int i = threadIdx.x; i < N_; i += blockDim.x) {
        if (g_validf[i] > 0.f) {
            float hp = g_hp[i];
            float maxA = decf(g_aE[i]);
            float maxB = decf(g_bE[i]);
            float hn = (maxB > hp - 0.5f) ? maxB : maxA;
            float base = fmaxf(hn - hp + 0.5f, 0.f);
            float w = (hp < 0.6f || hn > 0.3f) ? 2.0f : 1.0f;
            s += base * w + 0.5f * (1.0f - hp) + 0.5f * fmaxf(hn + 0.2f, 0.f);
            c += 1.f;
        }
    }
    __shared__ float rs[32], rc[32];
    for (int o = 16; o; o >>= 1) {
        s += __shfl_xor_sync(0xffffffffu, s, o);
        c += __shfl_xor_sync(0xffffffffu, c, o);
    }
    int wid = threadIdx.x >> 5, lane = threadIdx.x & 31;
    if (lane == 0) { rs[wid] = s; rc[wid] = c; }
    __syncthreads();
    int nw = (blockDim.x + 31) >> 5;
    if (wid == 0) {
        float vs = lane < nw ? rs[lane] : 0.f;
        float vc = lane < nw ? rc[lane] : 0.f;
        for (int o = 16; o; o >>= 1) {
            vs += __shfl_xor_sync(0xffffffffu, vs, o);
            vc += __shfl_xor_sync(0xffffffffu, vc, o);
        }
        if (lane == 0) out[0] = (vc > 0.f) ? (vs / vc) : 0.f;
    }
}

// ---------------- launcher ----------------
extern "C" void kernel_launch(void* const* d_in, const int* in_sizes, int n_in,
                              void* d_out, int out_size) {
    const float* emb = (const float*)d_in[0];
    const int* labels = (const int*)d_in[1];
    const int* pids = (const int*)d_in[2];
    float* out = (float*)d_out;

    cudaFuncSetAttribute(main_k, cudaFuncAttributeMaxDynamicSharedMemorySize, 196608);
    cudaFuncSetAttribute(hp_pid_k, cudaFuncAttributeMaxDynamicSharedMemorySize, 65536);

    normalize_k<<<N_, 64>>>(emb, labels, pids);
    hp_pid_k<<<NPID, 256, 65536>>>(labels, pids);
    main_k<<<NCTA, 512, 196608>>>(pids);
    finish_k<<<1, 1024>>>(out);
}

// round 10
// speedup vs baseline: 1.3003x; 1.0144x over previous
#include <cuda_runtime.h>
#include <cuda_fp16.h>
#include <cstdint>
#include <math.h>

#define N_    8192
#define D_    256
#define NPID  256
#define NB    64
#define TT    2080
#define NCTA  148
#define FIXS  1099511627776.f   // 2^40

__device__ float    g_normed[N_ * D_];
__device__ __half   g_nh[N_ * D_];
__device__ float    g_hp[N_];
__device__ float    g_validf[N_];
__device__ int      g_colsent[N_];
__device__ unsigned g_aE[N_];
__device__ unsigned g_bE[N_];
__device__ unsigned long long g_sumFx;
__device__ unsigned long long g_cntI;

__device__ __forceinline__ unsigned encf(float f) {
    unsigned u = __float_as_uint(f);
    return (u & 0x80000000u) ? ~u : (u | 0x80000000u);
}
__device__ __forceinline__ float decf(unsigned e) {
    unsigned u = (e & 0x80000000u) ? (e ^ 0x80000000u) : ~e;
    return __uint_as_float(u);
}
__device__ __forceinline__ uint32_t smem_u32(const void* p) {
    uint32_t a;
    asm("{ .reg .u64 t; cvta.to.shared.u64 t, %1; cvt.u32.u64 %0, t; }" : "=r"(a) : "l"(p));
    return a;
}
__device__ __forceinline__ void cpa16(uint32_t d, const void* s) {
    asm volatile("cp.async.cg.shared.global [%0], [%1], 16;" :: "r"(d), "l"(s) : "memory");
}
#define CP_COMMIT() asm volatile("cp.async.commit_group;" ::: "memory")
#define CP_WAIT(n)  asm volatile("cp.async.wait_group %0;" :: "n"(n) : "memory")

__device__ __forceinline__ void ldsm4(uint32_t& r0, uint32_t& r1, uint32_t& r2, uint32_t& r3,
                                      uint32_t addr) {
    asm volatile("ldmatrix.sync.aligned.m8n8.x4.shared.b16 {%0,%1,%2,%3}, [%4];"
                 : "=r"(r0), "=r"(r1), "=r"(r2), "=r"(r3) : "r"(addr));
}
__device__ __forceinline__ void mma16816(float& c0, float& c1, float& c2, float& c3,
                                         uint32_t a0, uint32_t a1, uint32_t a2, uint32_t a3,
                                         uint32_t b0, uint32_t b1) {
    asm volatile("mma.sync.aligned.m16n8k16.row.col.f32.f16.f16.f32 "
                 "{%0,%1,%2,%3},{%4,%5,%6,%7},{%8,%9},{%0,%1,%2,%3};"
                 : "+f"(c0), "+f"(c1), "+f"(c2), "+f"(c3)
                 : "r"(a0), "r"(a1), "r"(a2), "r"(a3), "r"(b0), "r"(b1));
}

__device__ __forceinline__ void dec_tri(int k, int& bi, int& bj) {
    int b = (int)((sqrtf(8.f * (float)k + 1.f) - 1.f) * 0.5f);
    while ((b + 1) * (b + 2) / 2 <= k) b++;
    while (b * (b + 1) / 2 > k) b--;
    bi = b;
    bj = k - b * (b + 1) / 2;
}

// ---------------- normalize: 4 rows/block, + sentinels + init ----------------
__global__ void normalize_k(const float* __restrict__ emb,
                            const int* __restrict__ labels,
                            const int* __restrict__ pids) {
    __shared__ float sred[4][2];
    int t = threadIdx.x;
    int rg = t >> 6, rt = t & 63;       // row group 0..3, thread-in-group
    int j = blockIdx.x * 4 + rg;
    float4 v = ((const float4*)(emb + (size_t)j * D_))[rt];
    float ss = v.x * v.x + v.y * v.y + v.z * v.z + v.w * v.w;
    for (int o = 16; o; o >>= 1) ss += __shfl_xor_sync(0xffffffffu, ss, o);
    if ((rt & 31) == 0) sred[rg][rt >> 5] = ss;
    __syncthreads();
    float inv = 1.0f / fmaxf(sqrtf(sred[rg][0] + sred[rg][1]), 1e-12f);
    float4 o4 = make_float4(v.x * inv, v.y * inv, v.z * inv, v.w * inv);
    ((float4*)(g_normed + (size_t)j * D_))[rt] = o4;
    __half2 h0 = __floats2half2_rn(o4.x, o4.y);
    __half2 h1 = __floats2half2_rn(o4.z, o4.w);
    ((__half2*)(g_nh + (size_t)j * D_ + rt * 4))[0] = h0;
    ((__half2*)(g_nh + (size_t)j * D_ + rt * 4))[1] = h1;
    if (rt == 0) {
        g_hp[j] = 1e9f;
        g_validf[j] = 0.f;
        unsigned e = encf(-1e9f);
        g_aE[j] = e;
        g_bE[j] = e;
        g_colsent[j] = (labels[j] == 1) ? pids[j] : -1;
    }
    if (j == 0 && rt == 0) { g_sumFx = 0ull; g_cntI = 0ull; }
}

// ------------- hardest positive: block per pid, scan + smem stage -------------
__global__ void __launch_bounds__(256, 1)
hp_pid_k(const int* __restrict__ labels, const int* __restrict__ pids) {
    extern __shared__ float srow[];
    __shared__ int slist[1024];
    __shared__ int sn;
    int p = blockIdx.x;
    if (threadIdx.x == 0) sn = 0;
    __syncthreads();
    for (int j = threadIdx.x; j < N_; j += 256)
        if (pids[j] == p && labels[j] == 1) {
            int q = atomicAdd(&sn, 1);
            if (q < 1024) slist[q] = j;
        }
    __syncthreads();
    int n = sn < 1024 ? sn : 1024;
    if (n == 0) return;
    int ns = (n < 64) ? n : 64;
    for (int idx = threadIdx.x; idx < ns * 64; idx += 256) {
        int m = idx >> 6, q = idx & 63;
        ((float4*)srow)[m * 64 + q] =
            ((const float4*)(g_normed + (size_t)slist[m] * D_))[q];
    }
    __syncthreads();
    int wid = threadIdx.x >> 5, lane = threadIdx.x & 31;
    float vf = (n >= 2) ? 1.f : 0.f;
    for (int a = wid; a < n; a += 8) {
        int i = slist[a];
        const float* arow = (a < ns) ? (srow + a * D_) : (g_normed + (size_t)i * D_);
        float a8[8];
#pragma unroll
        for (int k = 0; k < 8; k++) a8[k] = arow[k * 32 + lane];
        float hp = 1e9f;
        for (int j = 0; j < n; j++) {
            if (j == a) continue;
            const float* br = (j < ns) ? (srow + j * D_)
                                       : (g_normed + (size_t)slist[j] * D_);
            float s = 0.f;
#pragma unroll
            for (int k = 0; k < 8; k++) s = fmaf(a8[k], br[k * 32 + lane], s);
            for (int o = 16; o; o >>= 1) s += __shfl_xor_sync(0xffffffffu, s, o);
            hp = fminf(hp, s);
        }
        if (lane == 0) { g_hp[i] = hp; g_validf[i] = vf; }
    }
}

// -------- main: triangular mma.sync GEMM, row+column dual fold (unchanged) --------
__global__ void __launch_bounds__(512, 1)
main_k(const int* __restrict__ pids) {
    extern __shared__ char sm[];
    uint32_t sb = smem_u32(sm);
    const uint32_t A0 = sb, Bbuf0 = sb + 65536, Bbuf1 = sb + 131072;

    int tid = threadIdx.x, lane = tid & 31, wid = tid >> 5;
    int wr = (wid >> 2) * 32;
    int wc = (wid & 3) * 32;
    int gid = lane >> 2, tig = lane & 3;

    int k0 = (int)(((long long)blockIdx.x * TT) / NCTA);
    int k1 = (int)(((long long)(blockIdx.x + 1) * TT) / NCTA);
    if (k0 >= k1) return;

    int bi0, bj0;
    dec_tri(k0, bi0, bj0);

    {
        const __half* ga = g_nh + (size_t)bi0 * 128 * D_;
#pragma unroll
        for (int i = 0; i < 8; i++) {
            int id = tid + i * 512, r = id >> 5, c = id & 31;
            cpa16(A0 + r * 512 + ((c ^ (r & 7)) << 4), ga + r * 256 + c * 8);
        }
        const __half* gb = g_nh + (size_t)bj0 * 128 * D_;
#pragma unroll
        for (int i = 0; i < 8; i++) {
            int id = tid + i * 512, r = id >> 5, c = id & 31;
            cpa16(Bbuf0 + r * 512 + ((c ^ (r & 7)) << 4), gb + r * 256 + c * 8);
        }
        CP_COMMIT();
    }

    float hp_s[4], mA[4], mB[4];
    int pid_s[4], rsent[4];
    int cur_bi = bi0;
    {
#pragma unroll
        for (int m = 0; m < 2; m++) {
            int rA = bi0 * 128 + wr + m * 16 + gid;
            hp_s[2 * m] = g_hp[rA];         pid_s[2 * m] = pids[rA];     rsent[2 * m] = g_colsent[rA];
            hp_s[2 * m + 1] = g_hp[rA + 8]; pid_s[2 * m + 1] = pids[rA + 8]; rsent[2 * m + 1] = g_colsent[rA + 8];
        }
#pragma unroll
        for (int s = 0; s < 4; s++) { mA[s] = -1e9f; mB[s] = -1e9f; }
    }

    int arow = lane & 15;
    int kha = lane >> 4;
    int brow = ((lane >> 4) & 1) * 8 + (lane & 7);
    int khb = (lane >> 3) & 1;
    int xr = lane & 7;
    uint32_t aAddr[2];
#pragma unroll
    for (int m = 0; m < 2; m++) aAddr[m] = A0 + (wr + m * 16 + arow) * 512;

    for (int k = k0; k < k1; k++) {
        int bi, bj;
        dec_tri(k, bi, bj);

        if (bi != cur_bi) {
#pragma unroll
            for (int s = 0; s < 4; s++) {
                float a = mA[s], b = mB[s];
                for (int o = 1; o < 4; o <<= 1) {
                    a = fmaxf(a, __shfl_xor_sync(0xffffffffu, a, o));
                    b = fmaxf(b, __shfl_xor_sync(0xffffffffu, b, o));
                }
                if (tig == 0) {
                    int r = cur_bi * 128 + wr + (s >> 1) * 16 + (s & 1) * 8 + gid;
                    atomicMax(&g_aE[r], encf(a));
                    atomicMax(&g_bE[r], encf(b));
                }
                mA[s] = -1e9f; mB[s] = -1e9f;
            }
            const __half* ga = g_nh + (size_t)bi * 128 * D_;
#pragma unroll
            for (int i = 0; i < 8; i++) {
                int id = tid + i * 512, r = id >> 5, c = id & 31;
                cpa16(A0 + r * 512 + ((c ^ (r & 7)) << 4), ga + r * 256 + c * 8);
            }
            CP_COMMIT();
#pragma unroll
            for (int m = 0; m < 2; m++) {
                int rA = bi * 128 + wr + m * 16 + gid;
                hp_s[2 * m] = g_hp[rA];         pid_s[2 * m] = pids[rA];     rsent[2 * m] = g_colsent[rA];
                hp_s[2 * m + 1] = g_hp[rA + 8]; pid_s[2 * m + 1] = pids[rA + 8]; rsent[2 * m + 1] = g_colsent[rA + 8];
            }
            cur_bi = bi;
        }

        int pb = (k - k0) & 1;
        uint32_t Bc = pb ? Bbuf1 : Bbuf0;

        if (k + 1 < k1) {
            int nbi, nbj;
            dec_tri(k + 1, nbi, nbj);
            uint32_t Bn = pb ? Bbuf0 : Bbuf1;
            const __half* gs = g_nh + (size_t)nbj * 128 * D_;
#pragma unroll
            for (int i = 0; i < 8; i++) {
                int id = tid + i * 512, r = id >> 5, c = id & 31;
                cpa16(Bn + r * 512 + ((c ^ (r & 7)) << 4), gs + r * 256 + c * 8);
            }
            CP_COMMIT();
            CP_WAIT(1);
        } else {
            CP_WAIT(0);
        }
        __syncthreads();

        int cbase = bj * 128 + wc;
        int sv[4][2], pidc[4][2];
        float hpc[4][2];
#pragma unroll
        for (int n = 0; n < 4; n++) {
#pragma unroll
            for (int c = 0; c < 2; c++) {
                int cg = cbase + n * 8 + tig * 2 + c;
                sv[n][c] = __ldg(&g_colsent[cg]);
                pidc[n][c] = __ldg(&pids[cg]);
                hpc[n][c] = __ldg(&g_hp[cg]);
            }
        }

        uint32_t bAddr0 = Bc + (wc + brow) * 512;
        uint32_t bAddr1 = Bc + (wc + 16 + brow) * 512;

        float acc[2][4][4];
#pragma unroll
        for (int m = 0; m < 2; m++)
#pragma unroll
            for (int n = 0; n < 4; n++)
#pragma unroll
                for (int q = 0; q < 4; q++) acc[m][n][q] = 0.f;

#pragma unroll
        for (int ks = 0; ks < 16; ks++) {
            uint32_t aoff = (uint32_t)(((ks * 2 + kha) ^ xr) << 4);
            uint32_t boff = (uint32_t)(((ks * 2 + khb) ^ xr) << 4);
            uint32_t a[2][4], b[2][4];
#pragma unroll
            for (int m = 0; m < 2; m++)
                ldsm4(a[m][0], a[m][1], a[m][2], a[m][3], aAddr[m] + aoff);
            ldsm4(b[0][0], b[0][1], b[0][2], b[0][3], bAddr0 + boff);
            ldsm4(b[1][0], b[1][1], b[1][2], b[1][3], bAddr1 + boff);
#pragma unroll
            for (int m = 0; m < 2; m++) {
                mma16816(acc[m][0][0], acc[m][0][1], acc[m][0][2], acc[m][0][3],
                         a[m][0], a[m][1], a[m][2], a[m][3], b[0][0], b[0][1]);
                mma16816(acc[m][1][0], acc[m][1][1], acc[m][1][2], acc[m][1][3],
                         a[m][0], a[m][1], a[m][2], a[m][3], b[0][2], b[0][3]);
                mma16816(acc[m][2][0], acc[m][2][1], acc[m][2][2], acc[m][2][3],
                         a[m][0], a[m][1], a[m][2], a[m][3], b[1][0], b[1][1]);
                mma16816(acc[m][3][0], acc[m][3][1], acc[m][3][2], acc[m][3][3],
                         a[m][0], a[m][1], a[m][2], a[m][3], b[1][2], b[1][3]);
            }
        }

#pragma unroll
        for (int n = 0; n < 4; n++) {
#pragma unroll
            for (int m = 0; m < 2; m++) {
#pragma unroll
                for (int h = 0; h < 2; h++) {
                    int slot = 2 * m + h;
                    float hpv = hp_s[slot];
                    int mp = pid_s[slot];
                    float v0 = acc[m][n][h * 2 + 0];
                    float v1 = acc[m][n][h * 2 + 1];
                    bool c0k = (sv[n][0] == mp), c1k = (sv[n][1] == mp);
                    float a0 = c0k ? -1e9f : v0;
                    float a1 = c1k ? -1e9f : v1;
                    mA[slot] = fmaxf(mA[slot], fmaxf(a0, a1));
                    float b0 = (c0k || v0 >= hpv) ? -1e9f : v0;
                    float b1 = (c1k || v1 >= hpv) ? -1e9f : v1;
                    mB[slot] = fmaxf(mB[slot], fmaxf(b0, b1));
                }
            }
        }

#pragma unroll
        for (int n = 0; n < 4; n++) {
#pragma unroll
            for (int c = 0; c < 2; c++) {
                int pj = pidc[n][c];
                float hpj = hpc[n][c];
                float cA = -1e9f, cB = -1e9f;
#pragma unroll
                for (int m = 0; m < 2; m++) {
#pragma unroll
                    for (int h = 0; h < 2; h++) {
                        float v = acc[m][n][h * 2 + c];
                        bool kill = (rsent[2 * m + h] == pj);
                        cA = fmaxf(cA, kill ? -1e9f : v);
                        cB = fmaxf(cB, (kill || v >= hpj) ? -1e9f : v);
                    }
                }
                for (int o = 4; o < 32; o <<= 1) {
                    cA = fmaxf(cA, __shfl_xor_sync(0xffffffffu, cA, o));
                    cB = fmaxf(cB, __shfl_xor_sync(0xffffffffu, cB, o));
                }
                if (gid == 0) {
                    int cg = cbase + n * 8 + tig * 2 + c;
                    atomicMax(&g_aE[cg], encf(cA));
                    atomicMax(&g_bE[cg], encf(cB));
                }
            }
        }
        __syncthreads();
    }

#pragma unroll
    for (int s = 0; s < 4; s++) {
        float a = mA[s], b = mB[s];
        for (int o = 1; o < 4; o <<= 1) {
            a = fmaxf(a, __shfl_xor_sync(0xffffffffu, a, o));
            b = fmaxf(b, __shfl_xor_sync(0xffffffffu, b, o));
        }
        if (tig == 0) {
            int r = cur_bi * 128 + wr + (s >> 1) * 16 + (s & 1) * 8 + gid;
            atomicMax(&g_aE[r], encf(a));
            atomicMax(&g_bE[r], encf(b));
        }
    }
}

// ---------------- finish: 32-block fixed-point partial reduce ----------------
__global__ void finishA_k() {
    int i = blockIdx.x * 256 + threadIdx.x;
    float loss = 0.f;
    int vcnt = 0;
    if (g_validf[i] > 0.f) {
        float hp = g_hp[i];
        float maxA = decf(g_aE[i]);
        float maxB = decf(g_bE[i]);
        float hn = (maxB > hp - 0.5f) ? maxB : maxA;
        float base = fmaxf(hn - hp + 0.5f, 0.f);
        float w = (hp < 0.6f || hn > 0.3f) ? 2.0f : 1.0f;
        loss = base * w + 0.5f * (1.0f - hp) + 0.5f * fmaxf(hn + 0.2f, 0.f);
        vcnt = 1;
    }
    unsigned long long fx = (unsigned long long)__float2ull_rn(loss * FIXS);
    // warp then block reduce
    for (int o = 16; o; o >>= 1) {
        fx += __shfl_xor_sync(0xffffffffu, fx, o);
        vcnt += __shfl_xor_sync(0xffffffffu, vcnt, o);
    }
    __shared__ unsigned long long sfx[8];
    __shared__ int scnt[8];
    int wid = threadIdx.x >> 5, lane = threadIdx.x & 31;
    if (lane == 0) { sfx[wid] = fx; scnt[wid] = vcnt; }
    __syncthreads();
    if (wid == 0) {
        unsigned long long v = lane < 8 ? sfx[lane] : 0ull;
        int cc = lane < 8 ? scnt[lane] : 0;
        for (int o = 4; o; o >>= 1) {
            v += __shfl_xor_sync(0xffffffffu, v, o);
            cc += __shfl_xor_sync(0xffffffffu, cc, o);
        }
        if (lane == 0) {
            atomicAdd(&g_sumFx, v);
            atomicAdd(&g_cntI, (unsigned long long)cc);
        }
    }
}

__global__ void finishB_k(float* __restrict__ out) {
    unsigned long long s = g_sumFx, c = g_cntI;
    out[0] = (c > 0ull) ? (float)((double)s / (double)FIXS / (double)c) : 0.f;
}

// ---------------- launcher ----------------
extern "C" void kernel_launch(void* const* d_in, const int* in_sizes, int n_in,
                              void* d_out, int out_size) {
    const float* emb = (const float*)d_in[0];
    const int* labels = (const int*)d_in[1];
    const int* pids = (const int*)d_in[2];
    float* out = (float*)d_out;

    cudaFuncSetAttribute(main_k, cudaFuncAttributeMaxDynamicSharedMemorySize, 196608);
    cudaFuncSetAttribute(hp_pid_k, cudaFuncAttributeMaxDynamicSharedMemorySize, 65536);

    normalize_k<<<N_ / 4, 256>>>(emb, labels, pids);
    hp_pid_k<<<NPID, 256, 65536>>>(labels, pids);
    main_k<<<NCTA, 512, 196608>>>(pids);
    finishA_k<<<N_ / 256, 256>>>();
    finishB_k<<<1, 1>>>(out);
}

// round 11
// speedup vs baseline: 1.3550x; 1.0420x over previous
#include <cuda_runtime.h>
#include <cuda_fp16.h>
#include <cstdint>
#include <math.h>

#define N_    8192
#define D_    256
#define NPID  256
#define NB    64
#define TT    2080
#define NCTA  148
#define FIXS  1099511627776.f   // 2^40

__device__ float    g_normed[N_ * D_];
// pre-swizzled fp16: [block(64KB)][kchunk(16KB)][row(128B)][16B-unit ^ (row&7)]
__device__ __align__(16) __half g_swz[N_ * D_];
__device__ float    g_hp[N_];
__device__ float    g_validf[N_];
__device__ int      g_colsent[N_];
__device__ unsigned g_aE[N_];
__device__ unsigned g_bE[N_];
__device__ unsigned long long g_sumFx;
__device__ unsigned long long g_cntI;

__device__ __forceinline__ unsigned encf(float f) {
    unsigned u = __float_as_uint(f);
    return (u & 0x80000000u) ? ~u : (u | 0x80000000u);
}
__device__ __forceinline__ float decf(unsigned e) {
    unsigned u = (e & 0x80000000u) ? (e ^ 0x80000000u) : ~e;
    return __uint_as_float(u);
}
__device__ __forceinline__ uint32_t smem_u32(const void* p) {
    uint32_t a;
    asm("{ .reg .u64 t; cvta.to.shared.u64 t, %1; cvt.u32.u64 %0, t; }" : "=r"(a) : "l"(p));
    return a;
}
__device__ __forceinline__ void cpa16(uint32_t d, const void* s) {
    asm volatile("cp.async.cg.shared.global [%0], [%1], 16;" :: "r"(d), "l"(s) : "memory");
}
// thread's prior cp.asyncs arrive on mbarrier when complete (count pre-set)
__device__ __forceinline__ void cpa_mbar(uint32_t b) {
    asm volatile("cp.async.mbarrier.arrive.noinc.shared.b64 [%0];" :: "r"(b) : "memory");
}
__device__ __forceinline__ void bar_init(uint32_t b, uint32_t c) {
    asm volatile("mbarrier.init.shared.b64 [%0], %1;" :: "r"(b), "r"(c) : "memory");
}
__device__ __forceinline__ void bar_arrive(uint32_t b) {
    asm volatile("mbarrier.arrive.shared.b64 _, [%0];" :: "r"(b) : "memory");
}
__device__ __forceinline__ void bar_wait(uint32_t b, uint32_t ph) {
    asm volatile("{\n\t.reg .pred P;\n\tWL%=:\n\t"
                 "mbarrier.try_wait.parity.acquire.cta.shared::cta.b64 P, [%0], %1, 0x989680;\n\t"
                 "@P bra.uni WD%=;\n\tbra.uni WL%=;\n\tWD%=:\n\t}" :: "r"(b), "r"(ph) : "memory");
}
__device__ __forceinline__ void ldsm4(uint32_t& r0, uint32_t& r1, uint32_t& r2, uint32_t& r3,
                                      uint32_t addr) {
    asm volatile("ldmatrix.sync.aligned.m8n8.x4.shared.b16 {%0,%1,%2,%3}, [%4];"
                 : "=r"(r0), "=r"(r1), "=r"(r2), "=r"(r3) : "r"(addr));
}
__device__ __forceinline__ void mma16816(float& c0, float& c1, float& c2, float& c3,
                                         uint32_t a0, uint32_t a1, uint32_t a2, uint32_t a3,
                                         uint32_t b0, uint32_t b1) {
    asm volatile("mma.sync.aligned.m16n8k16.row.col.f32.f16.f16.f32 "
                 "{%0,%1,%2,%3},{%4,%5,%6,%7},{%8,%9},{%0,%1,%2,%3};"
                 : "+f"(c0), "+f"(c1), "+f"(c2), "+f"(c3)
                 : "r"(a0), "r"(a1), "r"(a2), "r"(a3), "r"(b0), "r"(b1));
}
__device__ __forceinline__ void dec_tri(int k, int& bi, int& bj) {
    int b = (int)((sqrtf(8.f * (float)k + 1.f) - 1.f) * 0.5f);
    while ((b + 1) * (b + 2) / 2 <= k) b++;
    while (b * (b + 1) / 2 > k) b--;
    bi = b;
    bj = k - b * (b + 1) / 2;
}

// ---------------- normalize: fp32 + pre-swizzled fp16 + init ----------------
__global__ void normalize_k(const float* __restrict__ emb,
                            const int* __restrict__ labels,
                            const int* __restrict__ pids) {
    __shared__ float sred[4][2];
    int t = threadIdx.x;
    int rg = t >> 6, rt = t & 63;
    int j = blockIdx.x * 4 + rg;
    float4 v = ((const float4*)(emb + (size_t)j * D_))[rt];
    float ss = v.x * v.x + v.y * v.y + v.z * v.z + v.w * v.w;
    for (int o = 16; o; o >>= 1) ss += __shfl_xor_sync(0xffffffffu, ss, o);
    if ((rt & 31) == 0) sred[rg][rt >> 5] = ss;
    __syncthreads();
    float inv = 1.0f / fmaxf(sqrtf(sred[rg][0] + sred[rg][1]), 1e-12f);
    float4 o4 = make_float4(v.x * inv, v.y * inv, v.z * inv, v.w * inv);
    ((float4*)(g_normed + (size_t)j * D_))[rt] = o4;
    __half2 h0 = __floats2half2_rn(o4.x, o4.y);
    __half2 h1 = __floats2half2_rn(o4.z, o4.w);
    // pre-swizzled write: 8 bytes at (block, chunk, row, permuted 16B unit)
    int b = j >> 7, r = j & 127;
    int c16 = rt >> 1, q = c16 >> 3, u = c16 & 7;
    char* dst = (char*)g_swz + (size_t)b * 65536 + q * 16384 + r * 128 +
                ((u ^ (r & 7)) << 4) + (rt & 1) * 8;
    *(__half2*)dst = h0;
    *(__half2*)(dst + 4) = h1;
    if (rt == 0) {
        g_hp[j] = 1e9f;
        g_validf[j] = 0.f;
        unsigned e = encf(-1e9f);
        g_aE[j] = e;
        g_bE[j] = e;
        g_colsent[j] = (labels[j] == 1) ? pids[j] : -1;
    }
    if (j == 0 && rt == 0) { g_sumFx = 0ull; g_cntI = 0ull; }
}

// ------------- hardest positive: block per pid, scan + smem stage -------------
__global__ void __launch_bounds__(256, 1)
hp_pid_k(const int* __restrict__ labels, const int* __restrict__ pids) {
    extern __shared__ float srow[];
    __shared__ int slist[1024];
    __shared__ int sn;
    int p = blockIdx.x;
    if (threadIdx.x == 0) sn = 0;
    __syncthreads();
    for (int j = threadIdx.x; j < N_; j += 256)
        if (pids[j] == p && labels[j] == 1) {
            int q = atomicAdd(&sn, 1);
            if (q < 1024) slist[q] = j;
        }
    __syncthreads();
    int n = sn < 1024 ? sn : 1024;
    if (n == 0) return;
    int ns = (n < 64) ? n : 64;
    for (int idx = threadIdx.x; idx < ns * 64; idx += 256) {
        int m = idx >> 6, q = idx & 63;
        ((float4*)srow)[m * 64 + q] =
            ((const float4*)(g_normed + (size_t)slist[m] * D_))[q];
    }
    __syncthreads();
    int wid = threadIdx.x >> 5, lane = threadIdx.x & 31;
    float vf = (n >= 2) ? 1.f : 0.f;
    for (int a = wid; a < n; a += 8) {
        int i = slist[a];
        const float* arow = (a < ns) ? (srow + a * D_) : (g_normed + (size_t)i * D_);
        float a8[8];
#pragma unroll
        for (int k = 0; k < 8; k++) a8[k] = arow[k * 32 + lane];
        float hp = 1e9f;
        for (int j = 0; j < n; j++) {
            if (j == a) continue;
            const float* br = (j < ns) ? (srow + j * D_)
                                       : (g_normed + (size_t)slist[j] * D_);
            float s = 0.f;
#pragma unroll
            for (int k = 0; k < 8; k++) s = fmaf(a8[k], br[k * 32 + lane], s);
            for (int o = 16; o; o >>= 1) s += __shfl_xor_sync(0xffffffffu, s, o);
            hp = fminf(hp, s);
        }
        if (lane == 0) { g_hp[i] = hp; g_validf[i] = vf; }
    }
}

// ---- main: triangular GEMM, mbarrier chunk pipeline, no steady-state syncs ----
__global__ void __launch_bounds__(512, 1)
main_k(const int* __restrict__ pids) {
    extern __shared__ char sm[];
    uint32_t sb = smem_u32(sm);
    const uint32_t A0 = sb, BST = sb + 65536;   // A 64K, B ring 8x16K
    __shared__ __align__(8) unsigned long long s_bar[17];
    uint32_t bar = smem_u32(s_bar);
#define FULLB(s) (bar + (s) * 8)
#define EMPTB(s) (bar + 64 + (s) * 8)
#define ABAR     (bar + 128)

    int tid = threadIdx.x, lane = tid & 31, wid = tid >> 5;
    int wr = (wid >> 2) * 32;
    int wc = (wid & 3) * 32;
    int gid = lane >> 2, tig = lane & 3;

    int k0 = (int)(((long long)blockIdx.x * TT) / NCTA);
    int k1 = (int)(((long long)(blockIdx.x + 1) * TT) / NCTA);
    if (k0 >= k1) return;
    int nch = (k1 - k0) * 4;

    if (tid == 0) {
        for (int s = 0; s < 8; s++) { bar_init(FULLB(s), 512); bar_init(EMPTB(s), 512); }
        bar_init(ABAR, 512);
    }
    __syncthreads();

    int bi0, bj0;
    dec_tri(k0, bi0, bj0);

    // prologue: A(bi0) + first 4 B chunks
    {
        const char* asrc = (const char*)g_swz + (size_t)bi0 * 65536;
#pragma unroll
        for (int i = 0; i < 8; i++)
            cpa16(A0 + i * 8192 + tid * 16, asrc + i * 8192 + tid * 16);
        cpa_mbar(ABAR);
    }
    int npro = nch < 4 ? nch : 4;
    for (int g = 0; g < npro; g++) {
        int tt = k0 + (g >> 2), bi, bj;
        dec_tri(tt, bi, bj);
        const char* src = (const char*)g_swz + (size_t)bj * 65536 + (size_t)(g & 3) * 16384;
        cpa16(BST + g * 16384 + tid * 16, src + tid * 16);
        cpa16(BST + g * 16384 + 8192 + tid * 16, src + 8192 + tid * 16);
        cpa_mbar(FULLB(g));
    }

    int ar = 0;
    bar_wait(ABAR, 0);

    float hp_s[4], mA[4], mB[4];
    int pid_s[4], rsent[4];
    int cur_bi = bi0;
#pragma unroll
    for (int m = 0; m < 2; m++) {
        int rA = bi0 * 128 + wr + m * 16 + gid;
        hp_s[2 * m] = g_hp[rA];         pid_s[2 * m] = pids[rA];     rsent[2 * m] = g_colsent[rA];
        hp_s[2 * m + 1] = g_hp[rA + 8]; pid_s[2 * m + 1] = pids[rA + 8]; rsent[2 * m + 1] = g_colsent[rA + 8];
    }
#pragma unroll
    for (int s = 0; s < 4; s++) { mA[s] = -1e9f; mB[s] = -1e9f; }

    int arow = lane & 15;
    int kha = lane >> 4;
    int brow = ((lane >> 4) & 1) * 8 + (lane & 7);
    int khb = (lane >> 3) & 1;
    int xr = lane & 7;

    for (int t = k0; t < k1; t++) {
        int bi, bj;
        dec_tri(t, bi, bj);

        if (bi != cur_bi) {
            // flush row maxes of cur_bi
#pragma unroll
            for (int s = 0; s < 4; s++) {
                float a = mA[s], b = mB[s];
                for (int o = 1; o < 4; o <<= 1) {
                    a = fmaxf(a, __shfl_xor_sync(0xffffffffu, a, o));
                    b = fmaxf(b, __shfl_xor_sync(0xffffffffu, b, o));
                }
                if (tig == 0) {
                    int r = cur_bi * 128 + wr + (s >> 1) * 16 + (s & 1) * 8 + gid;
                    atomicMax(&g_aE[r], encf(a));
                    atomicMax(&g_bE[r], encf(b));
                }
                mA[s] = -1e9f; mB[s] = -1e9f;
            }
            __syncthreads();   // all warps done reading old A
            const char* asrc = (const char*)g_swz + (size_t)bi * 65536;
#pragma unroll
            for (int i = 0; i < 8; i++)
                cpa16(A0 + i * 8192 + tid * 16, asrc + i * 8192 + tid * 16);
            cpa_mbar(ABAR);
            ar++;
            bar_wait(ABAR, ar & 1);
#pragma unroll
            for (int m = 0; m < 2; m++) {
                int rA = bi * 128 + wr + m * 16 + gid;
                hp_s[2 * m] = g_hp[rA];         pid_s[2 * m] = pids[rA];     rsent[2 * m] = g_colsent[rA];
                hp_s[2 * m + 1] = g_hp[rA + 8]; pid_s[2 * m + 1] = pids[rA + 8]; rsent[2 * m + 1] = g_colsent[rA + 8];
            }
            cur_bi = bi;
        }

        bool offdiag = (bi != bj);
        int cbase = bj * 128 + wc;
        int sv[4][2], pidc[4][2];
        float hpc[4][2];
#pragma unroll
        for (int n = 0; n < 4; n++) {
#pragma unroll
            for (int c = 0; c < 2; c++) {
                int cg = cbase + n * 8 + tig * 2 + c;
                sv[n][c] = __ldg(&g_colsent[cg]);
                if (offdiag) {
                    pidc[n][c] = __ldg(&pids[cg]);
                    hpc[n][c] = __ldg(&g_hp[cg]);
                }
            }
        }

        float acc[2][4][4];
#pragma unroll
        for (int m = 0; m < 2; m++)
#pragma unroll
            for (int n = 0; n < 4; n++)
#pragma unroll
                for (int q = 0; q < 4; q++) acc[m][n][q] = 0.f;

        int gbase = (t - k0) * 4;
#pragma unroll
        for (int q = 0; q < 4; q++) {
            int g = gbase + q, s = g & 7;
            bar_wait(FULLB(s), (g >> 3) & 1);
            uint32_t Bs = BST + s * 16384;
            uint32_t bAddr0 = Bs + (wc + brow) * 128;
            uint32_t bAddr1 = Bs + (wc + 16 + brow) * 128;
            uint32_t aBase = A0 + q * 16384;
#pragma unroll
            for (int l = 0; l < 4; l++) {
                uint32_t aoff = (uint32_t)(((l * 2 + kha) ^ xr) << 4);
                uint32_t boff = (uint32_t)(((l * 2 + khb) ^ xr) << 4);
                uint32_t a[2][4], b[2][4];
#pragma unroll
                for (int m = 0; m < 2; m++)
                    ldsm4(a[m][0], a[m][1], a[m][2], a[m][3],
                          aBase + (wr + m * 16 + arow) * 128 + aoff);
                ldsm4(b[0][0], b[0][1], b[0][2], b[0][3], bAddr0 + boff);
                ldsm4(b[1][0], b[1][1], b[1][2], b[1][3], bAddr1 + boff);
#pragma unroll
                for (int m = 0; m < 2; m++) {
                    mma16816(acc[m][0][0], acc[m][0][1], acc[m][0][2], acc[m][0][3],
                             a[m][0], a[m][1], a[m][2], a[m][3], b[0][0], b[0][1]);
                    mma16816(acc[m][1][0], acc[m][1][1], acc[m][1][2], acc[m][1][3],
                             a[m][0], a[m][1], a[m][2], a[m][3], b[0][2], b[0][3]);
                    mma16816(acc[m][2][0], acc[m][2][1], acc[m][2][2], acc[m][2][3],
                             a[m][0], a[m][1], a[m][2], a[m][3], b[1][0], b[1][1]);
                    mma16816(acc[m][3][0], acc[m][3][1], acc[m][3][2], acc[m][3][3],
                             a[m][0], a[m][1], a[m][2], a[m][3], b[1][2], b[1][3]);
                }
            }
            bar_arrive(EMPTB(s));   // this warp done with stage s (chunk g)

            int g2 = g + 4;         // refill 4 ahead (4-chunk reuse slack)
            if (g2 < nch) {
                int s2 = g2 & 7;
                if (g2 >= 8) bar_wait(EMPTB(s2), ((g2 - 8) >> 3) & 1);
                int t2 = k0 + (g2 >> 2), b2i, b2j;
                dec_tri(t2, b2i, b2j);
                const char* src = (const char*)g_swz + (size_t)b2j * 65536 +
                                  (size_t)(g2 & 3) * 16384;
                cpa16(BST + s2 * 16384 + tid * 16, src + tid * 16);
                cpa16(BST + s2 * 16384 + 8192 + tid * 16, src + 8192 + tid * 16);
                cpa_mbar(FULLB(s2));
            }
        }

        // row-anchor fold
#pragma unroll
        for (int n = 0; n < 4; n++) {
#pragma unroll
            for (int m = 0; m < 2; m++) {
#pragma unroll
                for (int h = 0; h < 2; h++) {
                    int slot = 2 * m + h;
                    float hpv = hp_s[slot];
                    int mp = pid_s[slot];
                    float v0 = acc[m][n][h * 2 + 0];
                    float v1 = acc[m][n][h * 2 + 1];
                    bool c0k = (sv[n][0] == mp), c1k = (sv[n][1] == mp);
                    float a0 = c0k ? -1e9f : v0;
                    float a1 = c1k ? -1e9f : v1;
                    mA[slot] = fmaxf(mA[slot], fmaxf(a0, a1));
                    float b0 = (c0k || v0 >= hpv) ? -1e9f : v0;
                    float b1 = (c1k || v1 >= hpv) ? -1e9f : v1;
                    mB[slot] = fmaxf(mB[slot], fmaxf(b0, b1));
                }
            }
        }

        // column-anchor fold (skip on diagonal tiles: redundant with row fold)
        if (offdiag) {
#pragma unroll
            for (int n = 0; n < 4; n++) {
#pragma unroll
                for (int c = 0; c < 2; c++) {
                    int pj = pidc[n][c];
                    float hpj = hpc[n][c];
                    float cA = -1e9f, cB = -1e9f;
#pragma unroll
                    for (int m = 0; m < 2; m++) {
#pragma unroll
                        for (int h = 0; h < 2; h++) {
                            float v = acc[m][n][h * 2 + c];
                            bool kill = (rsent[2 * m + h] == pj);
                            cA = fmaxf(cA, kill ? -1e9f : v);
                            cB = fmaxf(cB, (kill || v >= hpj) ? -1e9f : v);
                        }
                    }
                    for (int o = 4; o < 32; o <<= 1) {
                        cA = fmaxf(cA, __shfl_xor_sync(0xffffffffu, cA, o));
                        cB = fmaxf(cB, __shfl_xor_sync(0xffffffffu, cB, o));
                    }
                    if (gid == 0) {
                        int cg = cbase + n * 8 + tig * 2 + c;
                        atomicMax(&g_aE[cg], encf(cA));
                        atomicMax(&g_bE[cg], encf(cB));
                    }
                }
            }
        }
    }

    // final flush
#pragma unroll
    for (int s = 0; s < 4; s++) {
        float a = mA[s], b = mB[s];
        for (int o = 1; o < 4; o <<= 1) {
            a = fmaxf(a, __shfl_xor_sync(0xffffffffu, a, o));
            b = fmaxf(b, __shfl_xor_sync(0xffffffffu, b, o));
        }
        if (tig == 0) {
            int r = cur_bi * 128 + wr + (s >> 1) * 16 + (s & 1) * 8 + gid;
            atomicMax(&g_aE[r], encf(a));
            atomicMax(&g_bE[r], encf(b));
        }
    }
#undef FULLB
#undef EMPTB
#undef ABAR
}

// ---------------- finish: 32-block fixed-point partial reduce ----------------
__global__ void finishA_k() {
    int i = blockIdx.x * 256 + threadIdx.x;
    float loss = 0.f;
    int vcnt = 0;
    if (g_validf[i] > 0.f) {
        float hp = g_hp[i];
        float maxA = decf(g_aE[i]);
        float maxB = decf(g_bE[i]);
        float hn = (maxB > hp - 0.5f) ? maxB : maxA;
        float base = fmaxf(hn - hp + 0.5f, 0.f);
        float w = (hp < 0.6f || hn > 0.3f) ? 2.0f : 1.0f;
        loss = base * w + 0.5f * (1.0f - hp) + 0.5f * fmaxf(hn + 0.2f, 0.f);
        vcnt = 1;
    }
    unsigned long long fx = (unsigned long long)__float2ull_rn(loss * FIXS);
    for (int o = 16; o; o >>= 1) {
        fx += __shfl_xor_sync(0xffffffffu, fx, o);
        vcnt += __shfl_xor_sync(0xffffffffu, vcnt, o);
    }
    __shared__ unsigned long long sfx[8];
    __shared__ int scnt[8];
    int wid = threadIdx.x >> 5, lane = threadIdx.x & 31;
    if (lane == 0) { sfx[wid] = fx; scnt[wid] = vcnt; }
    __syncthreads();
    if (wid == 0) {
        unsigned long long v = lane < 8 ? sfx[lane] : 0ull;
        int cc = lane < 8 ? scnt[lane] : 0;
        for (int o = 4; o; o >>= 1) {
            v += __shfl_xor_sync(0xffffffffu, v, o);
            cc += __shfl_xor_sync(0xffffffffu, cc, o);
        }
        if (lane == 0) {
            atomicAdd(&g_sumFx, v);
            atomicAdd(&g_cntI, (unsigned long long)cc);
        }
    }
}

__global__ void finishB_k(float* __restrict__ out) {
    unsigned long long s = g_sumFx, c = g_cntI;
    out[0] = (c > 0ull) ? (float)((double)s / (double)FIXS / (double)c) : 0.f;
}

// ---------------- launcher ----------------
extern "C" void kernel_launch(void* const* d_in, const int* in_sizes, int n_in,
                              void* d_out, int out_size) {
    const float* emb = (const float*)d_in[0];
    const int* labels = (const int*)d_in[1];
    const int* pids = (const int*)d_in[2];
    float* out = (float*)d_out;

    cudaFuncSetAttribute(main_k, cudaFuncAttributeMaxDynamicSharedMemorySize, 196608);
    cudaFuncSetAttribute(hp_pid_k, cudaFuncAttributeMaxDynamicSharedMemorySize, 65536);

    normalize_k<<<N_ / 4, 256>>>(emb, labels, pids);
    hp_pid_k<<<NPID, 256, 65536>>>(labels, pids);
    main_k<<<NCTA, 512, 196608>>>(pids);
    finishA_k<<<N_ / 256, 256>>>();
    finishB_k<<<1, 1>>>(out);
}